// round 2
// baseline (speedup 1.0000x reference)
#include <cuda_runtime.h>
#include <math.h>

#define NN 200000
#define NUM_BAGS 25000
#define DD 690
#define RR 53
#define MAX_BAG 1024

__device__ float g_att[(size_t)NUM_BAGS * DD];  // 69 MB scratch
__device__ int g_is64;                          // index-dtype flag

// Detect whether scope/labels are int64 or int32.
// scope row 0 = (start0=0, end0>=1). As raw int32 words:
//   int32 layout: w[0]=0, w[1]=end0 (>=1)
//   int64 layout: w[0]=0, w[1]=high(start0)=0
__global__ void detect_dtype_kernel(const int* __restrict__ scope_raw)
{
    g_is64 = (scope_raw[1] == 0) ? 1 : 0;
}

__device__ __forceinline__ long long load_idx(const void* p, int i, int is64)
{
    return is64 ? ((const long long*)p)[i] : (long long)((const int*)p)[i];
}

__global__ __launch_bounds__(256) void bag_attn_kernel(
    const float* __restrict__ repre,
    const float* __restrict__ rel,
    const void*  __restrict__ scope,
    const void*  __restrict__ labels)
{
    __shared__ float s_rl[MAX_BAG];
    __shared__ float s_w[MAX_BAG];
    __shared__ int   s_is64;

    const int tid  = threadIdx.x;
    const int wid  = tid >> 5;
    const int lane = tid & 31;

    if (tid == 0) s_is64 = g_is64;
    __syncthreads();
    const int is64 = s_is64;

    const int b = blockIdx.x;
    int start = (int)load_idx(scope, 2 * b, is64);
    int end   = (int)load_idx(scope, 2 * b + 1, is64);
    // defensive clamps: wrong dtype yields wrong numbers, never a crash
    if (start < 0) start = 0;
    if (start > NN) start = NN;
    if (end < start) end = start;
    if (end > NN) end = NN;
    int nb = end - start;
    if (nb > MAX_BAG) nb = MAX_BAG;

    // ---- phase 1: per-instance relation logits (warp per instance) ----
    for (int j = wid; j < nb; j += 8) {
        const int i = start + j;
        int lab = (int)load_idx(labels, i, is64);
        if (lab < 0) lab = 0;
        if (lab >= RR) lab = RR - 1;
        const float* __restrict__ xr = repre + (size_t)i * DD;
        const float* __restrict__ rr = rel + (size_t)lab * DD;
        float acc = 0.0f;
        #pragma unroll 4
        for (int d = lane; d < DD; d += 32)
            acc += xr[d] * rr[d];
        #pragma unroll
        for (int o = 16; o > 0; o >>= 1)
            acc += __shfl_xor_sync(0xffffffffu, acc, o);
        if (lane == 0) s_rl[j] = acc;
    }
    __syncthreads();

    // ---- phase 2: softmax over the bag (warp 0) ----
    if (wid == 0) {
        float m = -INFINITY;
        for (int j = lane; j < nb; j += 32) m = fmaxf(m, s_rl[j]);
        #pragma unroll
        for (int o = 16; o > 0; o >>= 1)
            m = fmaxf(m, __shfl_xor_sync(0xffffffffu, m, o));
        float s = 0.0f;
        for (int j = lane; j < nb; j += 32) {
            float e = expf(s_rl[j] - m);
            s_w[j] = e;
            s += e;
        }
        #pragma unroll
        for (int o = 16; o > 0; o >>= 1)
            s += __shfl_xor_sync(0xffffffffu, s, o);
        float inv = 1.0f / s;
        for (int j = lane; j < nb; j += 32) s_w[j] *= inv;
    }
    __syncthreads();

    // ---- phase 3: weighted sum over bag rows (threads own 3 dims each) ----
    const int d0 = tid;
    const int d1 = tid + 256;
    const int d2 = tid + 512;
    float acc0 = 0.0f, acc1 = 0.0f, acc2 = 0.0f;
    for (int j = 0; j < nb; j++) {
        const float* __restrict__ xr = repre + (size_t)(start + j) * DD;
        const float w = s_w[j];
        acc0 += w * xr[d0];
        if (d1 < DD) acc1 += w * xr[d1];
        if (d2 < DD) acc2 += w * xr[d2];
    }
    float* __restrict__ outp = g_att + (size_t)b * DD;
    outp[d0] = acc0;
    if (d1 < DD) outp[d1] = acc1;
    if (d2 < DD) outp[d2] = acc2;
}

// logits = g_att @ rel^T + bias.  M=25000, K=690, N=53 (tile-padded to 64)
__global__ __launch_bounds__(128) void proj_gemm_kernel(
    const float* __restrict__ relp,
    const float* __restrict__ bias,
    float* __restrict__ out)
{
    const int M = NUM_BAGS;
    const int K = DD;

    __shared__ __align__(16) float As[32][68];
    __shared__ __align__(16) float Bs[32][68];

    const int tid = threadIdx.x;
    const int m0  = blockIdx.x * 64;
    const int tm  = (tid & 15) << 2;
    const int tn  = (tid >> 4) << 3;

    float acc[4][8];
    #pragma unroll
    for (int i = 0; i < 4; i++)
        #pragma unroll
        for (int j = 0; j < 8; j++) acc[i][j] = 0.0f;

    for (int kb = 0; kb < K; kb += 32) {
        #pragma unroll
        for (int t = tid; t < 64 * 32; t += 128) {
            const int r  = t >> 5;
            const int kk = t & 31;
            const int m  = m0 + r;
            const int k  = kb + kk;
            float v = 0.0f;
            if (m < M && k < K) v = g_att[(size_t)m * K + k];
            As[kk][r] = v;
        }
        #pragma unroll
        for (int t = tid; t < 64 * 32; t += 128) {
            const int n  = t >> 5;
            const int kk = t & 31;
            const int k  = kb + kk;
            float v = 0.0f;
            if (n < RR && k < K) v = relp[(size_t)n * K + k];
            Bs[kk][n] = v;
        }
        __syncthreads();

        #pragma unroll
        for (int k = 0; k < 32; k++) {
            const float4 a  = *(const float4*)&As[k][tm];
            const float4 b0 = *(const float4*)&Bs[k][tn];
            const float4 b1 = *(const float4*)&Bs[k][tn + 4];
            const float av[4] = {a.x, a.y, a.z, a.w};
            const float bv[8] = {b0.x, b0.y, b0.z, b0.w, b1.x, b1.y, b1.z, b1.w};
            #pragma unroll
            for (int i = 0; i < 4; i++)
                #pragma unroll
                for (int j = 0; j < 8; j++)
                    acc[i][j] = fmaf(av[i], bv[j], acc[i][j]);
        }
        __syncthreads();
    }

    #pragma unroll
    for (int i = 0; i < 4; i++) {
        const int m = m0 + tm + i;
        if (m >= M) continue;
        #pragma unroll
        for (int j = 0; j < 8; j++) {
            const int n = tn + j;
            if (n < RR) out[(size_t)m * RR + n] = acc[i][j] + bias[n];
        }
    }
}

extern "C" void kernel_launch(void* const* d_in, const int* in_sizes, int n_in,
                              void* d_out, int out_size)
{
    const float* repre  = (const float*)d_in[0];
    const float* relmat = (const float*)d_in[1];
    const float* bias   = (const float*)d_in[2];
    const void*  scope  = d_in[3];
    const void*  labels = d_in[4];
    float* out = (float*)d_out;

    detect_dtype_kernel<<<1, 1>>>((const int*)scope);
    bag_attn_kernel<<<NUM_BAGS, 256>>>(repre, relmat, scope, labels);
    proj_gemm_kernel<<<(NUM_BAGS + 63) / 64, 128>>>(relmat, bias, out);
}

// round 3
// speedup vs baseline: 1.0880x; 1.0880x over previous
#include <cuda_runtime.h>
#include <math.h>

#define NN 200000
#define NUM_BAGS 25000
#define DD 690
#define D2 345          // DD/2 float2s
#define RR 53
#define MAX_BAG 256

__device__ float g_att[(size_t)NUM_BAGS * DD];  // 69 MB scratch

// int64-vs-int32 sniff on raw scope words:
//   row0 = (start0=0, end0>=1). int32 layout: w[1]=end0>=1 ; int64 layout: w[1]=hi(start0)=0
__device__ __forceinline__ int sniff_is64(const void* scope)
{
    return (((const int*)scope)[1] == 0) ? 1 : 0;
}

__device__ __forceinline__ int load_idx(const void* p, int i, int is64)
{
    return is64 ? (int)((const long long*)p)[i] : ((const int*)p)[i];
}

__global__ __launch_bounds__(256) void bag_attn_kernel(
    const float* __restrict__ repre,
    const float* __restrict__ rel,
    const void*  __restrict__ scope,
    const void*  __restrict__ labels)
{
    __shared__ float s_rl[MAX_BAG];
    __shared__ float s_w[MAX_BAG];

    const int tid  = threadIdx.x;
    const int wid  = tid >> 5;
    const int lane = tid & 31;
    const int is64 = sniff_is64(scope);

    const int b = blockIdx.x;
    int start = load_idx(scope, 2 * b, is64);
    int end   = load_idx(scope, 2 * b + 1, is64);
    if (start < 0) start = 0;
    if (start > NN) start = NN;
    if (end < start) end = start;
    if (end > NN) end = NN;
    int nb = end - start;
    if (nb > MAX_BAG) nb = MAX_BAG;

    // ---- phase 1: per-instance relation logit (warp per instance, float2) ----
    for (int j = wid; j < nb; j += 8) {
        const int i = start + j;
        int lab = load_idx(labels, i, is64);
        if (lab < 0) lab = 0;
        if (lab >= RR) lab = RR - 1;
        const float2* __restrict__ xr2 = (const float2*)(repre + (size_t)i * DD);
        const float2* __restrict__ rr2 = (const float2*)(rel + (size_t)lab * DD);
        float acc = 0.0f;
        #pragma unroll
        for (int it = 0; it < 10; it++) {
            const int d = lane + 32 * it;          // < 320
            const float2 x = xr2[d];
            const float2 r = rr2[d];
            acc = fmaf(x.x, r.x, acc);
            acc = fmaf(x.y, r.y, acc);
        }
        {   // tail: indices 320..344
            const int d = 320 + lane;
            if (d < D2) {
                const float2 x = xr2[d];
                const float2 r = rr2[d];
                acc = fmaf(x.x, r.x, acc);
                acc = fmaf(x.y, r.y, acc);
            }
        }
        #pragma unroll
        for (int o = 16; o > 0; o >>= 1)
            acc += __shfl_xor_sync(0xffffffffu, acc, o);
        if (lane == 0) s_rl[j] = acc;
    }
    __syncthreads();

    // ---- phase 2: softmax over the bag (warp 0) ----
    if (wid == 0) {
        float m = -INFINITY;
        for (int j = lane; j < nb; j += 32) m = fmaxf(m, s_rl[j]);
        #pragma unroll
        for (int o = 16; o > 0; o >>= 1)
            m = fmaxf(m, __shfl_xor_sync(0xffffffffu, m, o));
        float s = 0.0f;
        for (int j = lane; j < nb; j += 32) {
            float e = expf(s_rl[j] - m);
            s_w[j] = e;
            s += e;
        }
        #pragma unroll
        for (int o = 16; o > 0; o >>= 1)
            s += __shfl_xor_sync(0xffffffffu, s, o);
        float inv = 1.0f / s;
        for (int j = lane; j < nb; j += 32) s_w[j] *= inv;
    }
    __syncthreads();

    // ---- phase 3: weighted bag sum (float2 per thread, rows L1-hot) ----
    const int f0 = tid;          // < 256 < 345 always
    const int f1 = tid + 256;    // active when tid < 89
    const bool has1 = (f1 < D2);
    float2 a0 = make_float2(0.0f, 0.0f);
    float2 a1 = make_float2(0.0f, 0.0f);

    int j = 0;
    for (; j + 1 < nb; j += 2) {
        const float2* __restrict__ xA = (const float2*)(repre + (size_t)(start + j) * DD);
        const float2* __restrict__ xB = (const float2*)(repre + (size_t)(start + j + 1) * DD);
        const float wA = s_w[j];
        const float wB = s_w[j + 1];
        const float2 vA0 = xA[f0];
        const float2 vB0 = xB[f0];
        a0.x = fmaf(wA, vA0.x, a0.x); a0.y = fmaf(wA, vA0.y, a0.y);
        a0.x = fmaf(wB, vB0.x, a0.x); a0.y = fmaf(wB, vB0.y, a0.y);
        if (has1) {
            const float2 vA1 = xA[f1];
            const float2 vB1 = xB[f1];
            a1.x = fmaf(wA, vA1.x, a1.x); a1.y = fmaf(wA, vA1.y, a1.y);
            a1.x = fmaf(wB, vB1.x, a1.x); a1.y = fmaf(wB, vB1.y, a1.y);
        }
    }
    if (j < nb) {
        const float2* __restrict__ xA = (const float2*)(repre + (size_t)(start + j) * DD);
        const float wA = s_w[j];
        const float2 vA0 = xA[f0];
        a0.x = fmaf(wA, vA0.x, a0.x); a0.y = fmaf(wA, vA0.y, a0.y);
        if (has1) {
            const float2 vA1 = xA[f1];
            a1.x = fmaf(wA, vA1.x, a1.x); a1.y = fmaf(wA, vA1.y, a1.y);
        }
    }

    float2* __restrict__ outp = (float2*)(g_att + (size_t)b * DD);
    outp[f0] = a0;
    if (has1) outp[f1] = a1;
}

// ---------------------------------------------------------------------------
// K2: logits = g_att @ rel^T + bias.  M=25000, K=690, N=53 (tiles padded to 64)
// BM=64, BN=64, BK=32, 256 threads, 4x4 microtile, float2 global loads.
// ---------------------------------------------------------------------------
__global__ __launch_bounds__(256) void proj_gemm_kernel(
    const float* __restrict__ relp,
    const float* __restrict__ bias,
    float* __restrict__ out)
{
    const int M = NUM_BAGS;
    const int K = DD;

    __shared__ __align__(16) float As[32][68];  // [kk][m]
    __shared__ __align__(16) float Bs[32][68];  // [kk][n]

    const int tid = threadIdx.x;
    const int m0  = blockIdx.x * 64;
    const int tm  = (tid & 15) << 2;   // 0..60
    const int tn  = (tid >> 4) << 2;   // 0..60

    float acc[4][4];
    #pragma unroll
    for (int i = 0; i < 4; i++)
        #pragma unroll
        for (int jj = 0; jj < 4; jj++) acc[i][jj] = 0.0f;

    for (int kb = 0; kb < K; kb += 32) {
        // A tile: 64 rows x 32 k = 1024 f2, 4 f2/thread
        #pragma unroll
        for (int s = 0; s < 4; s++) {
            const int q   = tid + 256 * s;      // 0..1023
            const int r   = q >> 4;             // row in tile
            const int kk2 = (q & 15) << 1;      // even k within tile
            const int m   = m0 + r;
            const int k   = kb + kk2;
            float2 v = make_float2(0.0f, 0.0f);
            if (m < M && k + 1 < K)
                v = *(const float2*)(g_att + (size_t)m * K + k);
            As[kk2][r]     = v.x;
            As[kk2 + 1][r] = v.y;
        }
        // B tile: 64 n x 32 k = 1024 f2 (rows >= 53 zero)
        #pragma unroll
        for (int s = 0; s < 4; s++) {
            const int q   = tid + 256 * s;
            const int n   = q >> 4;
            const int kk2 = (q & 15) << 1;
            const int k   = kb + kk2;
            float2 v = make_float2(0.0f, 0.0f);
            if (n < RR && k + 1 < K)
                v = *(const float2*)(relp + (size_t)n * K + k);
            Bs[kk2][n]     = v.x;
            Bs[kk2 + 1][n] = v.y;
        }
        __syncthreads();

        #pragma unroll
        for (int k = 0; k < 32; k++) {
            const float4 a = *(const float4*)&As[k][tm];
            const float4 bvec = *(const float4*)&Bs[k][tn];
            const float av[4] = {a.x, a.y, a.z, a.w};
            const float bv[4] = {bvec.x, bvec.y, bvec.z, bvec.w};
            #pragma unroll
            for (int i = 0; i < 4; i++)
                #pragma unroll
                for (int jj = 0; jj < 4; jj++)
                    acc[i][jj] = fmaf(av[i], bv[jj], acc[i][jj]);
        }
        __syncthreads();
    }

    #pragma unroll
    for (int i = 0; i < 4; i++) {
        const int m = m0 + tm + i;
        if (m >= M) continue;
        #pragma unroll
        for (int jj = 0; jj < 4; jj++) {
            const int n = tn + jj;
            if (n < RR) out[(size_t)m * RR + n] = acc[i][jj] + bias[n];
        }
    }
}

extern "C" void kernel_launch(void* const* d_in, const int* in_sizes, int n_in,
                              void* d_out, int out_size)
{
    const float* repre  = (const float*)d_in[0];
    const float* relmat = (const float*)d_in[1];
    const float* bias   = (const float*)d_in[2];
    const void*  scope  = d_in[3];
    const void*  labels = d_in[4];
    float* out = (float*)d_out;

    bag_attn_kernel<<<NUM_BAGS, 256>>>(repre, relmat, scope, labels);
    proj_gemm_kernel<<<(NUM_BAGS + 63) / 64, 256>>>(relmat, bias, out);
}